// round 12
// baseline (speedup 1.0000x reference)
#include <cuda_runtime.h>
#include <cuda_fp16.h>
#include <stdint.h>

// ---------------------------------------------------------------------------
// Channel attention, factorized; classic tensor cores mma.m16n8k16 fp16->f32.
//   P[b]  = q @ x[b]^T                   1-MMA fp16, split-K=2 (f32 partials)
//   E[b]  = kw . P[b] + kb (x) qsum      2-MMA (kw hi/lo split)
//   att   = softmax rows(E)              fused with transpose -> aTh fp16
//   W2[b] = attT . vwT                   1-MMA
//   out   = gamma*(W2 @ xT + b2) + x     1-MMA, f32 epilogue + residual
// R11: two-stream overlap (wprep + xT-prep under GEMM1; bias2 under GEMM3).
// ---------------------------------------------------------------------------

#define BATCH 8
#define CCH   512
#define NPIX  4096

__device__ __half g_xh [BATCH*CCH*NPIX];
__device__ __half g_xTh[BATCH*CCH*NPIX];
__device__ __half g_qh [CCH*NPIX];
__device__ __half g_kwh[CCH*CCH];
__device__ __half g_kwl[CCH*CCH];
__device__ __half g_vwTh[CCH*CCH];
__device__ __half g_Ph [BATCH*CCH*CCH];
__device__ __half g_aTh[BATCH*CCH*CCH];
__device__ __half g_W2h[BATCH*CCH*CCH];
__device__ float g_Pp[2*BATCH*CCH*CCH];   // split-K partials for GEMM1
__device__ float g_E[BATCH*CCH*CCH];
__device__ float g_qsum[CCH];
__device__ float g_bias2[BATCH*CCH];

// --------------------------- asm helpers -----------------------------------
__device__ __forceinline__ uint32_t smem_u32(const void* p) {
    uint32_t a;
    asm("{ .reg .u64 t; cvta.to.shared.u64 t, %1; cvt.u32.u64 %0, t; }" : "=r"(a) : "l"(p));
    return a;
}
__device__ __forceinline__ void cp16(uint32_t saddr, const void* g) {
    asm volatile("cp.async.cg.shared.global [%0], [%1], 16;" :: "r"(saddr), "l"(g) : "memory");
}
__device__ __forceinline__ void cp_commit() {
    asm volatile("cp.async.commit_group;" ::: "memory");
}
template<int N>
__device__ __forceinline__ void cp_wait() {
    asm volatile("cp.async.wait_group %0;" :: "n"(N) : "memory");
}
__device__ __forceinline__ void ldsm4(uint32_t* r, uint32_t a) {
    asm volatile("ldmatrix.sync.aligned.m8n8.x4.shared.b16 {%0,%1,%2,%3}, [%4];"
                 : "=r"(r[0]), "=r"(r[1]), "=r"(r[2]), "=r"(r[3]) : "r"(a));
}
__device__ __forceinline__ void mma16816(float* d, const uint32_t* a, const uint32_t* b) {
    asm volatile("mma.sync.aligned.m16n8k16.row.col.f32.f16.f16.f32 "
                 "{%0,%1,%2,%3}, {%4,%5,%6,%7}, {%8,%9}, {%0,%1,%2,%3};"
                 : "+f"(d[0]), "+f"(d[1]), "+f"(d[2]), "+f"(d[3])
                 : "r"(a[0]), "r"(a[1]), "r"(a[2]), "r"(a[3]), "r"(b[0]), "r"(b[1]));
}
__device__ __forceinline__ uint32_t pack2(__half a, __half b) {
    __half2 p; p.x = a; p.y = b;
    return *reinterpret_cast<uint32_t*>(&p);
}

// --------------------------- GEMM kernel -----------------------------------
#define RSB   80
#define TILEB 10240

// EPI: 1 = f32 + e1[m]*e2[n]; 2 = gamma*(v+e1)+xres; 3 = half out; 4 = f32 plain.
template<int NMMA, int EPI, bool KSPLIT>
__global__ __launch_bounds__(256)
void gemm_f16(const __half* __restrict__ Ah, const __half* __restrict__ Al,
              const __half* __restrict__ Bh,
              int ldA, int ldB, long sA, long sB, int K,
              __half* __restrict__ Dh,
              float* __restrict__ Dout, int ldD, long sD,
              const float* __restrict__ e1, long se1,
              const float* __restrict__ e2,
              const float* __restrict__ xres,
              const float* __restrict__ gptr)
{
    constexpr int NTILES = (NMMA == 2) ? 3 : 2;
    constexpr int STGB   = NTILES * TILEB;
    constexpr int BOFF   = (NMMA == 2) ? 2 * TILEB : TILEB;

    extern __shared__ char sm[];
    const uint32_t sb = smem_u32(sm);
    const int tid = threadIdx.x, lane = tid & 31, wid = tid >> 5;
    const int wm = (wid >> 2) * 64, wn = (wid & 3) * 32;
    const int b      = KSPLIT ? (blockIdx.z & 7) : blockIdx.z;
    const int kslice = KSPLIT ? (blockIdx.z >> 3) : 0;
    const int m0 = blockIdx.y * 128, n0 = blockIdx.x * 128;

    Ah += b * sA + (long)kslice * K;
    if (NMMA == 2) Al += (long)kslice * K;
    Bh += b * sB + (long)kslice * K;
    if (KSPLIT) Dout += (long)kslice * BATCH * sD;

    const uint32_t aoff = ((lane & 7) + 8 * ((lane >> 3) & 1)) * RSB + (lane >> 4) * 16;
    const uint32_t boff = ((lane & 7) + 8 * (lane >> 4)) * RSB + ((lane >> 3) & 1) * 16;

    const int r0c = tid >> 2;
    const int c16 = tid & 3;

    float acc[4][4][4];
    #pragma unroll
    for (int i = 0; i < 4; i++)
        #pragma unroll
        for (int j = 0; j < 4; j++)
            #pragma unroll
            for (int v = 0; v < 4; v++) acc[i][j][v] = 0.f;

    const int nc = K >> 5;

    auto load_stage = [&](int stage, int k0) {
        uint32_t base = sb + stage * STGB;
        #pragma unroll
        for (int i = 0; i < 2; i++) {
            int row = r0c + i * 64;
            uint32_t so = base + row * RSB + c16 * 16;
            long ga = (long)(m0 + row) * ldA + k0 + c16 * 8;
            cp16(so, Ah + ga);
            if (NMMA == 2) cp16(so + TILEB, Al + ga);
            cp16(so + BOFF, Bh + (long)(n0 + row) * ldB + k0 + c16 * 8);
        }
    };

    auto compute_stage = [&](int stage) {
        uint32_t Abase = sb + stage * STGB;
        uint32_t Bbase = Abase + BOFF;
        #pragma unroll
        for (int ks = 0; ks < 2; ks++) {
            uint32_t kb2 = ks * 32;
            uint32_t ah[4][4], al[4][4], bh[4][2];
            #pragma unroll
            for (int mi = 0; mi < 4; mi++) {
                ldsm4(ah[mi], Abase + (wm + mi * 16) * RSB + kb2 + aoff);
                if (NMMA == 2) ldsm4(al[mi], Abase + TILEB + (wm + mi * 16) * RSB + kb2 + aoff);
            }
            #pragma unroll
            for (int nb = 0; nb < 2; nb++) {
                uint32_t t[4];
                ldsm4(t, Bbase + (wn + nb * 16) * RSB + kb2 + boff);
                bh[2*nb][0] = t[0]; bh[2*nb][1] = t[1];
                bh[2*nb+1][0] = t[2]; bh[2*nb+1][1] = t[3];
            }
            #pragma unroll
            for (int mi = 0; mi < 4; mi++)
                #pragma unroll
                for (int ni = 0; ni < 4; ni++) {
                    mma16816(acc[mi][ni], ah[mi], bh[ni]);
                    if (NMMA == 2) mma16816(acc[mi][ni], al[mi], bh[ni]);
                }
        }
    };

    load_stage(0, 0);
    cp_commit();
    if (nc > 1) load_stage(1, 32);
    cp_commit();
    for (int c = 0; c < nc; c++) {
        cp_wait<1>();
        __syncthreads();
        if (c + 2 < nc) load_stage((c + 2) % 3, (c + 2) * 32);
        cp_commit();
        compute_stage(c % 3);
    }

    // ------------------------------ epilogue -------------------------------
    float g = 0.f;
    if (EPI == 2) g = gptr[0];
    #pragma unroll
    for (int mi = 0; mi < 4; mi++) {
        #pragma unroll
        for (int half_ = 0; half_ < 2; half_++) {
            int r = m0 + wm + mi * 16 + (lane >> 2) + half_ * 8;
            float e1r = 0.f;
            if (EPI == 1) e1r = e1[r];
            if (EPI == 2) e1r = e1[b * se1 + r];
            #pragma unroll
            for (int ni = 0; ni < 4; ni++) {
                int cidx = n0 + wn + ni * 8 + 2 * (lane & 3);
                float v0 = acc[mi][ni][half_ * 2 + 0];
                float v1 = acc[mi][ni][half_ * 2 + 1];
                long idx = (long)r * ldD + cidx;
                if (EPI == 3) {
                    __half2 ph;
                    ph.x = __float2half_rn(v0); ph.y = __float2half_rn(v1);
                    *reinterpret_cast<__half2*>(Dh + b * sD + idx) = ph;
                } else if (EPI == 4) {
                    float2 o; o.x = v0; o.y = v1;
                    *reinterpret_cast<float2*>(Dout + b * sD + idx) = o;
                } else if (EPI == 1) {
                    float2 o;
                    o.x = v0 + e1r * e2[cidx];
                    o.y = v1 + e1r * e2[cidx + 1];
                    *reinterpret_cast<float2*>(Dout + b * sD + idx) = o;
                } else {
                    float2 xr = *reinterpret_cast<const float2*>(xres + b * sD + idx);
                    float2 o;
                    o.x = g * (v0 + e1r) + xr.x;
                    o.y = g * (v1 + e1r) + xr.y;
                    *reinterpret_cast<float2*>(Dout + b * sD + idx) = o;
                }
            }
        }
    }
}

// split-K reduction: Ph = half(p0 + p1)
__global__ __launch_bounds__(256)
void reduceP_kernel(const float4* __restrict__ p0, const float4* __restrict__ p1,
                    uint2* __restrict__ Ph)
{
    int i = blockIdx.x * 256 + threadIdx.x;
    float4 a = p0[i], c = p1[i];
    uint2 u;
    u.x = pack2(__float2half_rn(a.x + c.x), __float2half_rn(a.y + c.y));
    u.y = pack2(__float2half_rn(a.z + c.z), __float2half_rn(a.w + c.w));
    Ph[i] = u;
}

// ------------------------- prep kernels ------------------------------------
// pure streaming convert x -> xh (critical path for GEMM1)
__global__ __launch_bounds__(256)
void xh_kernel(const float4* __restrict__ in, uint2* __restrict__ oh)
{
    int i = blockIdx.x * 256 + threadIdx.x;
    float4 v = in[i];
    uint2 u;
    u.x = pack2(__float2half_rn(v.x), __float2half_rn(v.y));
    u.y = pack2(__float2half_rn(v.z), __float2half_rn(v.w));
    oh[i] = u;
}

// transpose-convert x -> xTh (NxC fp16), overlapped with GEMM1
__global__ __launch_bounds__(256)
void xT_kernel(const float* __restrict__ x, __half* __restrict__ xTh)
{
    __shared__ __half t[64][66];
    const int b  = blockIdx.z;
    const int n0 = blockIdx.x * 64, c0 = blockIdx.y * 64;
    const int tx = threadIdx.x & 15, ty = threadIdx.x >> 4;
    const long sb_ = (long)b * CCH * NPIX;
    const float* xb = x + sb_;

    #pragma unroll
    for (int i = 0; i < 4; i++) {
        int cl = ty + 16 * i;
        float4 v = *reinterpret_cast<const float4*>(xb + (long)(c0 + cl) * NPIX + n0 + tx * 4);
        *reinterpret_cast<uint32_t*>(&t[cl][tx * 4])     = pack2(__float2half_rn(v.x), __float2half_rn(v.y));
        *reinterpret_cast<uint32_t*>(&t[cl][tx * 4 + 2]) = pack2(__float2half_rn(v.z), __float2half_rn(v.w));
    }
    __syncthreads();
    #pragma unroll
    for (int i = 0; i < 4; i++) {
        int nl = ty + 16 * i;
        uint2 u;
        u.x = pack2(t[tx*4+0][nl], t[tx*4+1][nl]);
        u.y = pack2(t[tx*4+2][nl], t[tx*4+3][nl]);
        *reinterpret_cast<uint2*>(xTh + sb_ + (long)(n0 + nl) * CCH + c0 + tx * 4) = u;
    }
}

// q: convert to fp16 + row sums (qsum). One block per d row.
__global__ __launch_bounds__(256)
void qprep_kernel(const float* __restrict__ q, __half* __restrict__ qh)
{
    const int d = blockIdx.x, tid = threadIdx.x;
    const float4* row = reinterpret_cast<const float4*>(q + (long)d * NPIX);
    uint2* orow = reinterpret_cast<uint2*>(qh + (long)d * NPIX);
    float s = 0.f;
    #pragma unroll
    for (int j = 0; j < 4; j++) {
        int i = tid + j * 256;
        float4 v = row[i];
        s += v.x + v.y + v.z + v.w;
        uint2 u;
        u.x = pack2(__float2half_rn(v.x), __float2half_rn(v.y));
        u.y = pack2(__float2half_rn(v.z), __float2half_rn(v.w));
        orow[i] = u;
    }
    #pragma unroll
    for (int o = 16; o; o >>= 1) s += __shfl_xor_sync(0xffffffffu, s, o);
    __shared__ float sh[8];
    if ((tid & 31) == 0) sh[tid >> 5] = s;
    __syncthreads();
    if (tid == 0) {
        float t = 0.f;
        #pragma unroll
        for (int i = 0; i < 8; i++) t += sh[i];
        g_qsum[d] = t;
    }
}

// kw hi/lo convert (blocks 0..255) + vw transpose->fp16 (blocks 256..511)
__global__ __launch_bounds__(256)
void wprep_kernel(const float* __restrict__ kw, const float* __restrict__ vw,
                  uint2* __restrict__ kwh, uint2* __restrict__ kwl,
                  __half* __restrict__ vwTh)
{
    __shared__ float smf[32][33];
    if (blockIdx.x < 256) {
        int i = blockIdx.x * 256 + threadIdx.x;
        float4 v = reinterpret_cast<const float4*>(kw)[i];
        float f[4] = {v.x, v.y, v.z, v.w};
        __half h[4], l[4];
        #pragma unroll
        for (int j = 0; j < 4; j++) {
            h[j] = __float2half_rn(f[j]);
            l[j] = __float2half_rn(f[j] - __half2float(h[j]));
        }
        uint2 uh, ul;
        uh.x = pack2(h[0], h[1]); uh.y = pack2(h[2], h[3]);
        ul.x = pack2(l[0], l[1]); ul.y = pack2(l[2], l[3]);
        kwh[i] = uh; kwl[i] = ul;
    } else {
        int t = blockIdx.x - 256;
        int x0 = (t & 15) * 32, y0 = (t >> 4) * 32;
        int tx = threadIdx.x & 31, ty = threadIdx.x >> 5;
        #pragma unroll
        for (int i = 0; i < 4; i++)
            smf[ty + i * 8][tx] = vw[(long)(y0 + ty + i * 8) * CCH + x0 + tx];
        __syncthreads();
        #pragma unroll
        for (int i = 0; i < 4; i++)
            vwTh[(long)(x0 + ty + i * 8) * CCH + y0 + tx] = __float2half_rn(smf[tx][ty + i * 8]);
    }
}

// fused softmax (rows of g_E) + transposed fp16 write to aTh
__global__ __launch_bounds__(256)
void smtrans_kernel(__half* __restrict__ aTh)
{
    __shared__ __half s[8][512];
    const int w = threadIdx.x >> 5, lane = threadIdx.x & 31;
    const long r = (long)blockIdx.x * 8 + w;
    const float* row = g_E + r * CCH;

    float v[16];
    float m = -1e30f;
    #pragma unroll
    for (int k = 0; k < 16; k++) { v[k] = row[lane + 32 * k]; m = fmaxf(m, v[k]); }
    #pragma unroll
    for (int o = 16; o; o >>= 1) m = fmaxf(m, __shfl_xor_sync(0xffffffffu, m, o));
    float ss = 0.f;
    #pragma unroll
    for (int k = 0; k < 16; k++) { v[k] = expf(v[k] - m); ss += v[k]; }
    #pragma unroll
    for (int o = 16; o; o >>= 1) ss += __shfl_xor_sync(0xffffffffu, ss, o);
    float inv = 1.f / ss;
    #pragma unroll
    for (int k = 0; k < 16; k++)
        s[w][lane + 32 * k] = __float2half_rn(v[k] * inv);
    __syncthreads();

    const int b  = (blockIdx.x * 8) >> 9;
    const int c0 = (blockIdx.x * 8) & 511;
    __half* out = aTh + (long)b * CCH * CCH + c0;
    #pragma unroll
    for (int dd = 0; dd < 2; dd++) {
        int d = 2 * threadIdx.x + dd;
        uint4 u;
        u.x = pack2(s[0][d], s[1][d]);
        u.y = pack2(s[2][d], s[3][d]);
        u.z = pack2(s[4][d], s[5][d]);
        u.w = pack2(s[6][d], s[7][d]);
        *reinterpret_cast<uint4*>(out + (long)d * CCH) = u;
    }
}

// bias2[b,c] = sum_d aTh[(b,c)][d]*vb[d]
__global__ __launch_bounds__(256)
void bias2_kernel(const __half* __restrict__ aTh, const float* __restrict__ vb)
{
    const int row = blockIdx.x * 8 + (threadIdx.x >> 5);
    const int lane = threadIdx.x & 31;
    const __half* ar = aTh + (long)row * CCH;
    float s = 0.f;
    #pragma unroll
    for (int k = 0; k < 16; k++) {
        int d = lane + 32 * k;
        s += __half2float(ar[d]) * vb[d];
    }
    #pragma unroll
    for (int o = 16; o; o >>= 1) s += __shfl_xor_sync(0xffffffffu, s, o);
    if (lane == 0) g_bias2[row] = s;
}

// ---------------------------------------------------------------------------
extern "C" void kernel_launch(void* const* d_in, const int* in_sizes, int n_in,
                              void* d_out, int out_size)
{
    const float* x     = (const float*)d_in[0];
    const float* q     = (const float*)d_in[1];
    const float* kw    = (const float*)d_in[2];
    const float* kb    = (const float*)d_in[3];
    const float* vw    = (const float*)d_in[4];
    const float* vb    = (const float*)d_in[5];
    const float* gamma = (const float*)d_in[6];
    float* out = (float*)d_out;

    const int SM1 = 3 * 2 * TILEB;   // 61440
    const int SM2 = 3 * 3 * TILEB;   // 92160
    cudaFuncSetAttribute((const void*)gemm_f16<1,4,true>,  cudaFuncAttributeMaxDynamicSharedMemorySize, SM1);
    cudaFuncSetAttribute((const void*)gemm_f16<1,2,false>, cudaFuncAttributeMaxDynamicSharedMemorySize, SM1);
    cudaFuncSetAttribute((const void*)gemm_f16<1,3,false>, cudaFuncAttributeMaxDynamicSharedMemorySize, SM1);
    cudaFuncSetAttribute((const void*)gemm_f16<2,1,false>, cudaFuncAttributeMaxDynamicSharedMemorySize, SM2);

    __half *xh, *xTh, *qh, *kwh, *kwl, *vwTh, *Ph, *aTh, *W2h;
    float *pE, *pq, *pb2, *pPp;
    cudaGetSymbolAddress((void**)&xh,  g_xh);
    cudaGetSymbolAddress((void**)&xTh, g_xTh);
    cudaGetSymbolAddress((void**)&qh,  g_qh);
    cudaGetSymbolAddress((void**)&kwh, g_kwh);
    cudaGetSymbolAddress((void**)&kwl, g_kwl);
    cudaGetSymbolAddress((void**)&vwTh,g_vwTh);
    cudaGetSymbolAddress((void**)&Ph,  g_Ph);
    cudaGetSymbolAddress((void**)&aTh, g_aTh);
    cudaGetSymbolAddress((void**)&W2h, g_W2h);
    cudaGetSymbolAddress((void**)&pPp, g_Pp);
    cudaGetSymbolAddress((void**)&pE,  g_E);
    cudaGetSymbolAddress((void**)&pq,  g_qsum);
    cudaGetSymbolAddress((void**)&pb2, g_bias2);

    const long sCC = (long)CCH * CCH;
    const long sCN = (long)CCH * NPIX;

    // one-time side-stream + events (created on correctness run, reused in capture)
    static cudaStream_t s1 = 0;
    static cudaEvent_t evFork = 0, evPrep = 0, evSM = 0, evB2 = 0;
    if (!s1) {
        cudaStreamCreateWithFlags(&s1, cudaStreamNonBlocking);
        cudaEventCreateWithFlags(&evFork, cudaEventDisableTiming);
        cudaEventCreateWithFlags(&evPrep, cudaEventDisableTiming);
        cudaEventCreateWithFlags(&evSM,   cudaEventDisableTiming);
        cudaEventCreateWithFlags(&evB2,   cudaEventDisableTiming);
    }

    // ---- fork side stream ----
    cudaEventRecord(evFork, 0);
    cudaStreamWaitEvent(s1, evFork, 0);

    // ---- s1: weights prep + x transpose (needed only from GEMM2/3/4 on) ----
    wprep_kernel<<<512, 256, 0, s1>>>(kw, vw, (uint2*)kwh, (uint2*)kwl, vwTh);
    xT_kernel<<<dim3(NPIX/64, CCH/64, BATCH), 256, 0, s1>>>(x, xTh);
    cudaEventRecord(evPrep, s1);

    // ---- s0: critical path ----
    qprep_kernel<<<CCH, 256>>>(q, qh);
    xh_kernel<<<(BATCH*CCH*NPIX/4)/256, 256>>>((const float4*)x, (uint2*)xh);

    // GEMM1 (split-K=2): Pp[s][b][d][c] = sum_{n in slice s} q[d][n]*x[b][c][n]
    gemm_f16<1,4,true><<<dim3(4,4,16), 256, SM1>>>(
        qh, (const __half*)0, xh, NPIX, NPIX, 0, sCN, 2048,
        (__half*)0, pPp, CCH, sCC,
        (const float*)0, 0, (const float*)0, (const float*)0, (const float*)0);

    reduceP_kernel<<<(BATCH*CCH*CCH/4)/256, 256>>>(
        (const float4*)pPp, (const float4*)(pPp + BATCH*sCC), (uint2*)Ph);

    // join: GEMM2 needs kwh/kwl (and later kernels need vwTh/xTh)
    cudaStreamWaitEvent(0, evPrep, 0);

    // GEMM2: E[b][c][d] = sum_k kw[c][k]*P[b][d][k] + kb[c]*qsum[d] (kw split)
    gemm_f16<2,1,false><<<dim3(4,4,BATCH), 256, SM2>>>(
        kwh, kwl, Ph, CCH, CCH, 0, sCC, CCH,
        (__half*)0, pE, CCH, sCC,
        kb, 0, pq, (const float*)0, (const float*)0);

    // fused softmax + transpose
    smtrans_kernel<<<BATCH*CCH/8, 256>>>(aTh);
    cudaEventRecord(evSM, 0);

    // s1: bias2 runs beside GEMM3
    cudaStreamWaitEvent(s1, evSM, 0);
    bias2_kernel<<<BATCH*CCH/8, 256, 0, s1>>>(aTh, vb);
    cudaEventRecord(evB2, s1);

    // GEMM3: W2[b][c][o] = sum_d attT[c][d]*vwT[o][d]
    gemm_f16<1,3,false><<<dim3(4,4,BATCH), 256, SM1>>>(
        aTh, (const __half*)0, vwTh, CCH, CCH, sCC, 0, CCH,
        W2h, (float*)0, CCH, sCC,
        (const float*)0, 0, (const float*)0, (const float*)0, (const float*)0);

    // join bias2 before GEMM4
    cudaStreamWaitEvent(0, evB2, 0);

    // GEMM4: out = gamma*(W2 @ xT + bias2) + x
    gemm_f16<1,2,false><<<dim3(NPIX/128, 4, BATCH), 256, SM1>>>(
        W2h, (const __half*)0, xTh, CCH, CCH, sCC, sCN, CCH,
        (__half*)0, out, NPIX, sCN,
        pb2, CCH, (const float*)0, x, gamma);
}

// round 13
// speedup vs baseline: 1.3772x; 1.3772x over previous
#include <cuda_runtime.h>
#include <cuda_fp16.h>
#include <stdint.h>

// ---------------------------------------------------------------------------
// Channel attention, factorized; classic tensor cores mma.m16n8k16 fp16->f32.
//   P[b]  = q @ x[b]^T                   1-MMA fp16, split-K=2, CTA 128x256
//   E[b]  = kw . P[b] + kb (x) qsum      2-MMA (kw hi/lo split), CTA 128x128
//   att   = softmax rows(E)              fused with transpose -> aTh fp16
//   W2[b] = attT . vwT                   1-MMA, CTA 128x128
//   out   = gamma*(W2 @ xT + b2) + x     1-MMA, CTA 128x256
// R13: single stream (R12 streams regressed); 64x64 warp tiles on big GEMMs.
// ---------------------------------------------------------------------------

#define BATCH 8
#define CCH   512
#define NPIX  4096

__device__ __half g_xh [BATCH*CCH*NPIX];
__device__ __half g_xTh[BATCH*CCH*NPIX];
__device__ __half g_qh [CCH*NPIX];
__device__ __half g_kwh[CCH*CCH];
__device__ __half g_kwl[CCH*CCH];
__device__ __half g_vwTh[CCH*CCH];
__device__ __half g_Ph [BATCH*CCH*CCH];
__device__ __half g_aTh[BATCH*CCH*CCH];
__device__ __half g_W2h[BATCH*CCH*CCH];
__device__ float g_Pp[2*BATCH*CCH*CCH];
__device__ float g_E[BATCH*CCH*CCH];
__device__ float g_qsum[CCH];
__device__ float g_bias2[BATCH*CCH];

// --------------------------- asm helpers -----------------------------------
__device__ __forceinline__ uint32_t smem_u32(const void* p) {
    uint32_t a;
    asm("{ .reg .u64 t; cvta.to.shared.u64 t, %1; cvt.u32.u64 %0, t; }" : "=r"(a) : "l"(p));
    return a;
}
__device__ __forceinline__ void cp16(uint32_t saddr, const void* g) {
    asm volatile("cp.async.cg.shared.global [%0], [%1], 16;" :: "r"(saddr), "l"(g) : "memory");
}
__device__ __forceinline__ void cp_commit() {
    asm volatile("cp.async.commit_group;" ::: "memory");
}
template<int N>
__device__ __forceinline__ void cp_wait() {
    asm volatile("cp.async.wait_group %0;" :: "n"(N) : "memory");
}
__device__ __forceinline__ void ldsm4(uint32_t* r, uint32_t a) {
    asm volatile("ldmatrix.sync.aligned.m8n8.x4.shared.b16 {%0,%1,%2,%3}, [%4];"
                 : "=r"(r[0]), "=r"(r[1]), "=r"(r[2]), "=r"(r[3]) : "r"(a));
}
__device__ __forceinline__ void mma16816(float* d, const uint32_t* a, const uint32_t* b) {
    asm volatile("mma.sync.aligned.m16n8k16.row.col.f32.f16.f16.f32 "
                 "{%0,%1,%2,%3}, {%4,%5,%6,%7}, {%8,%9}, {%0,%1,%2,%3};"
                 : "+f"(d[0]), "+f"(d[1]), "+f"(d[2]), "+f"(d[3])
                 : "r"(a[0]), "r"(a[1]), "r"(a[2]), "r"(a[3]), "r"(b[0]), "r"(b[1]));
}
__device__ __forceinline__ uint32_t pack2(__half a, __half b) {
    __half2 p; p.x = a; p.y = b;
    return *reinterpret_cast<uint32_t*>(&p);
}

// --------------------------- GEMM kernel -----------------------------------
// CTA tile 128 x BN (BN = 128 or 256), BK=32, 3-stage cp.async pipeline.
// 8 warps, 2x4 warp grid, warp tile 64 x (BN/4).
#define RSB   80
#define ATILE 10240

// EPI: 1 = f32 + e1[m]*e2[n]; 2 = gamma*(v+e1)+xres; 3 = half out; 4 = f32 plain.
template<int NMMA, int EPI, bool KSPLIT, int BN>
__global__ __launch_bounds__(256)
void gemm_f16(const __half* __restrict__ Ah, const __half* __restrict__ Al,
              const __half* __restrict__ Bh,
              int ldA, int ldB, long sA, long sB, int K,
              __half* __restrict__ Dh,
              float* __restrict__ Dout, int ldD, long sD,
              const float* __restrict__ e1, long se1,
              const float* __restrict__ e2,
              const float* __restrict__ xres,
              const float* __restrict__ gptr)
{
    constexpr int BTILE = BN * RSB;
    constexpr int BOFF  = (NMMA == 2) ? 2 * ATILE : ATILE;
    constexpr int STGB  = BOFF + BTILE;
    constexpr int NBLK  = BN / 64;         // B ldsm4 per warp per ks (2 or 4)
    constexpr int NI    = 2 * NBLK;        // n8 mma frags per warp

    extern __shared__ char sm[];
    const uint32_t sb = smem_u32(sm);
    const int tid = threadIdx.x, lane = tid & 31, wid = tid >> 5;
    const int wm = (wid >> 2) * 64, wn = (wid & 3) * (BN / 4);
    const int b      = KSPLIT ? (blockIdx.z & 7) : blockIdx.z;
    const int kslice = KSPLIT ? (blockIdx.z >> 3) : 0;
    const int m0 = blockIdx.y * 128, n0 = blockIdx.x * BN;

    Ah += b * sA + (long)kslice * K;
    if (NMMA == 2) Al += (long)kslice * K;
    Bh += b * sB + (long)kslice * K;
    if (KSPLIT) Dout += (long)kslice * BATCH * sD;

    const uint32_t aoff = ((lane & 7) + 8 * ((lane >> 3) & 1)) * RSB + (lane >> 4) * 16;
    const uint32_t boff = ((lane & 7) + 8 * (lane >> 4)) * RSB + ((lane >> 3) & 1) * 16;

    const int r0c = tid >> 2;
    const int c16 = tid & 3;

    float acc[4][NI][4];
    #pragma unroll
    for (int i = 0; i < 4; i++)
        #pragma unroll
        for (int j = 0; j < NI; j++)
            #pragma unroll
            for (int v = 0; v < 4; v++) acc[i][j][v] = 0.f;

    const int nc = K >> 5;

    auto load_stage = [&](int stage, int k0) {
        uint32_t base = sb + stage * STGB;
        #pragma unroll
        for (int i = 0; i < 2; i++) {
            int row = r0c + i * 64;
            uint32_t so = base + row * RSB + c16 * 16;
            long ga = (long)(m0 + row) * ldA + k0 + c16 * 8;
            cp16(so, Ah + ga);
            if (NMMA == 2) cp16(so + ATILE, Al + ga);
        }
        #pragma unroll
        for (int i = 0; i < BN / 64; i++) {
            int row = r0c + i * 64;
            uint32_t so = base + BOFF + row * RSB + c16 * 16;
            cp16(so, Bh + (long)(n0 + row) * ldB + k0 + c16 * 8);
        }
    };

    auto compute_stage = [&](int stage) {
        uint32_t Abase = sb + stage * STGB;
        uint32_t Bbase = Abase + BOFF;
        #pragma unroll
        for (int ks = 0; ks < 2; ks++) {
            uint32_t kb2 = ks * 32;
            uint32_t ah[4][4], al[4][4], bh[NI][2];
            #pragma unroll
            for (int mi = 0; mi < 4; mi++) {
                ldsm4(ah[mi], Abase + (wm + mi * 16) * RSB + kb2 + aoff);
                if (NMMA == 2) ldsm4(al[mi], Abase + ATILE + (wm + mi * 16) * RSB + kb2 + aoff);
            }
            #pragma unroll
            for (int nb = 0; nb < NBLK; nb++) {
                uint32_t t[4];
                ldsm4(t, Bbase + (wn + nb * 16) * RSB + kb2 + boff);
                bh[2*nb][0] = t[0]; bh[2*nb][1] = t[1];
                bh[2*nb+1][0] = t[2]; bh[2*nb+1][1] = t[3];
            }
            #pragma unroll
            for (int mi = 0; mi < 4; mi++)
                #pragma unroll
                for (int ni = 0; ni < NI; ni++) {
                    mma16816(acc[mi][ni], ah[mi], bh[ni]);
                    if (NMMA == 2) mma16816(acc[mi][ni], al[mi], bh[ni]);
                }
        }
    };

    load_stage(0, 0);
    cp_commit();
    if (nc > 1) load_stage(1, 32);
    cp_commit();
    for (int c = 0; c < nc; c++) {
        cp_wait<1>();
        __syncthreads();
        if (c + 2 < nc) load_stage((c + 2) % 3, (c + 2) * 32);
        cp_commit();
        compute_stage(c % 3);
    }

    // ------------------------------ epilogue -------------------------------
    float g = 0.f;
    if (EPI == 2) g = gptr[0];
    #pragma unroll
    for (int mi = 0; mi < 4; mi++) {
        #pragma unroll
        for (int half_ = 0; half_ < 2; half_++) {
            int r = m0 + wm + mi * 16 + (lane >> 2) + half_ * 8;
            float e1r = 0.f;
            if (EPI == 1) e1r = e1[r];
            if (EPI == 2) e1r = e1[b * se1 + r];
            #pragma unroll
            for (int ni = 0; ni < NI; ni++) {
                int cidx = n0 + wn + ni * 8 + 2 * (lane & 3);
                float v0 = acc[mi][ni][half_ * 2 + 0];
                float v1 = acc[mi][ni][half_ * 2 + 1];
                long idx = (long)r * ldD + cidx;
                if (EPI == 3) {
                    __half2 ph;
                    ph.x = __float2half_rn(v0); ph.y = __float2half_rn(v1);
                    *reinterpret_cast<__half2*>(Dh + b * sD + idx) = ph;
                } else if (EPI == 4) {
                    float2 o; o.x = v0; o.y = v1;
                    *reinterpret_cast<float2*>(Dout + b * sD + idx) = o;
                } else if (EPI == 1) {
                    float2 o;
                    o.x = v0 + e1r * e2[cidx];
                    o.y = v1 + e1r * e2[cidx + 1];
                    *reinterpret_cast<float2*>(Dout + b * sD + idx) = o;
                } else {
                    float2 xr = *reinterpret_cast<const float2*>(xres + b * sD + idx);
                    float2 o;
                    o.x = g * (v0 + e1r) + xr.x;
                    o.y = g * (v1 + e1r) + xr.y;
                    *reinterpret_cast<float2*>(Dout + b * sD + idx) = o;
                }
            }
        }
    }
}

// split-K reduction: Ph = half(p0 + p1)
__global__ __launch_bounds__(256)
void reduceP_kernel(const float4* __restrict__ p0, const float4* __restrict__ p1,
                    uint2* __restrict__ Ph)
{
    int i = blockIdx.x * 256 + threadIdx.x;
    float4 a = p0[i], c = p1[i];
    uint2 u;
    u.x = pack2(__float2half_rn(a.x + c.x), __float2half_rn(a.y + c.y));
    u.y = pack2(__float2half_rn(a.z + c.z), __float2half_rn(a.w + c.w));
    Ph[i] = u;
}

// ------------------------- prep kernels ------------------------------------
// x: convert to fp16 (CxN) and transposed fp16 (NxC). 64x64 tiles, vector I/O.
__global__ __launch_bounds__(256)
void xprep_kernel(const float* __restrict__ x,
                  __half* __restrict__ xh, __half* __restrict__ xTh)
{
    __shared__ __half t[64][66];
    const int b  = blockIdx.z;
    const int n0 = blockIdx.x * 64, c0 = blockIdx.y * 64;
    const int tx = threadIdx.x & 15, ty = threadIdx.x >> 4;
    const long sb_ = (long)b * CCH * NPIX;
    const float* xb = x + sb_;

    #pragma unroll
    for (int i = 0; i < 4; i++) {
        int cl = ty + 16 * i;
        float4 v = *reinterpret_cast<const float4*>(xb + (long)(c0 + cl) * NPIX + n0 + tx * 4);
        uint32_t p0 = pack2(__float2half_rn(v.x), __float2half_rn(v.y));
        uint32_t p1 = pack2(__float2half_rn(v.z), __float2half_rn(v.w));
        uint2 u; u.x = p0; u.y = p1;
        *reinterpret_cast<uint2*>(xh + sb_ + (long)(c0 + cl) * NPIX + n0 + tx * 4) = u;
        *reinterpret_cast<uint32_t*>(&t[cl][tx * 4])     = p0;
        *reinterpret_cast<uint32_t*>(&t[cl][tx * 4 + 2]) = p1;
    }
    __syncthreads();
    #pragma unroll
    for (int i = 0; i < 4; i++) {
        int nl = ty + 16 * i;
        uint2 u;
        u.x = pack2(t[tx*4+0][nl], t[tx*4+1][nl]);
        u.y = pack2(t[tx*4+2][nl], t[tx*4+3][nl]);
        *reinterpret_cast<uint2*>(xTh + sb_ + (long)(n0 + nl) * CCH + c0 + tx * 4) = u;
    }
}

// q: convert to fp16 + row sums (qsum). One block per d row.
__global__ __launch_bounds__(256)
void qprep_kernel(const float* __restrict__ q, __half* __restrict__ qh)
{
    const int d = blockIdx.x, tid = threadIdx.x;
    const float4* row = reinterpret_cast<const float4*>(q + (long)d * NPIX);
    uint2* orow = reinterpret_cast<uint2*>(qh + (long)d * NPIX);
    float s = 0.f;
    #pragma unroll
    for (int j = 0; j < 4; j++) {
        int i = tid + j * 256;
        float4 v = row[i];
        s += v.x + v.y + v.z + v.w;
        uint2 u;
        u.x = pack2(__float2half_rn(v.x), __float2half_rn(v.y));
        u.y = pack2(__float2half_rn(v.z), __float2half_rn(v.w));
        orow[i] = u;
    }
    #pragma unroll
    for (int o = 16; o; o >>= 1) s += __shfl_xor_sync(0xffffffffu, s, o);
    __shared__ float sh[8];
    if ((tid & 31) == 0) sh[tid >> 5] = s;
    __syncthreads();
    if (tid == 0) {
        float t = 0.f;
        #pragma unroll
        for (int i = 0; i < 8; i++) t += sh[i];
        g_qsum[d] = t;
    }
}

// kw hi/lo convert (blocks 0..255) + vw transpose->fp16 (blocks 256..511)
__global__ __launch_bounds__(256)
void wprep_kernel(const float* __restrict__ kw, const float* __restrict__ vw,
                  uint2* __restrict__ kwh, uint2* __restrict__ kwl,
                  __half* __restrict__ vwTh)
{
    __shared__ float smf[32][33];
    if (blockIdx.x < 256) {
        int i = blockIdx.x * 256 + threadIdx.x;
        float4 v = reinterpret_cast<const float4*>(kw)[i];
        float f[4] = {v.x, v.y, v.z, v.w};
        __half h[4], l[4];
        #pragma unroll
        for (int j = 0; j < 4; j++) {
            h[j] = __float2half_rn(f[j]);
            l[j] = __float2half_rn(f[j] - __half2float(h[j]));
        }
        uint2 uh, ul;
        uh.x = pack2(h[0], h[1]); uh.y = pack2(h[2], h[3]);
        ul.x = pack2(l[0], l[1]); ul.y = pack2(l[2], l[3]);
        kwh[i] = uh; kwl[i] = ul;
    } else {
        int t = blockIdx.x - 256;
        int x0 = (t & 15) * 32, y0 = (t >> 4) * 32;
        int tx = threadIdx.x & 31, ty = threadIdx.x >> 5;
        #pragma unroll
        for (int i = 0; i < 4; i++)
            smf[ty + i * 8][tx] = vw[(long)(y0 + ty + i * 8) * CCH + x0 + tx];
        __syncthreads();
        #pragma unroll
        for (int i = 0; i < 4; i++)
            vwTh[(long)(x0 + ty + i * 8) * CCH + y0 + tx] = __float2half_rn(smf[tx][ty + i * 8]);
    }
}

// fused softmax (rows of g_E) + transposed fp16 write to aTh
__global__ __launch_bounds__(256)
void smtrans_kernel(__half* __restrict__ aTh)
{
    __shared__ __half s[8][512];
    const int w = threadIdx.x >> 5, lane = threadIdx.x & 31;
    const long r = (long)blockIdx.x * 8 + w;
    const float* row = g_E + r * CCH;

    float v[16];
    float m = -1e30f;
    #pragma unroll
    for (int k = 0; k < 16; k++) { v[k] = row[lane + 32 * k]; m = fmaxf(m, v[k]); }
    #pragma unroll
    for (int o = 16; o; o >>= 1) m = fmaxf(m, __shfl_xor_sync(0xffffffffu, m, o));
    float ss = 0.f;
    #pragma unroll
    for (int k = 0; k < 16; k++) { v[k] = expf(v[k] - m); ss += v[k]; }
    #pragma unroll
    for (int o = 16; o; o >>= 1) ss += __shfl_xor_sync(0xffffffffu, ss, o);
    float inv = 1.f / ss;
    #pragma unroll
    for (int k = 0; k < 16; k++)
        s[w][lane + 32 * k] = __float2half_rn(v[k] * inv);
    __syncthreads();

    const int b  = (blockIdx.x * 8) >> 9;
    const int c0 = (blockIdx.x * 8) & 511;
    __half* out = aTh + (long)b * CCH * CCH + c0;
    #pragma unroll
    for (int dd = 0; dd < 2; dd++) {
        int d = 2 * threadIdx.x + dd;
        uint4 u;
        u.x = pack2(s[0][d], s[1][d]);
        u.y = pack2(s[2][d], s[3][d]);
        u.z = pack2(s[4][d], s[5][d]);
        u.w = pack2(s[6][d], s[7][d]);
        *reinterpret_cast<uint4*>(out + (long)d * CCH) = u;
    }
}

// bias2[b,c] = sum_d aTh[(b,c)][d]*vb[d]
__global__ __launch_bounds__(256)
void bias2_kernel(const __half* __restrict__ aTh, const float* __restrict__ vb)
{
    const int row = blockIdx.x * 8 + (threadIdx.x >> 5);
    const int lane = threadIdx.x & 31;
    const __half* ar = aTh + (long)row * CCH;
    float s = 0.f;
    #pragma unroll
    for (int k = 0; k < 16; k++) {
        int d = lane + 32 * k;
        s += __half2float(ar[d]) * vb[d];
    }
    #pragma unroll
    for (int o = 16; o; o >>= 1) s += __shfl_xor_sync(0xffffffffu, s, o);
    if (lane == 0) g_bias2[row] = s;
}

// ---------------------------------------------------------------------------
extern "C" void kernel_launch(void* const* d_in, const int* in_sizes, int n_in,
                              void* d_out, int out_size)
{
    const float* x     = (const float*)d_in[0];
    const float* q     = (const float*)d_in[1];
    const float* kw    = (const float*)d_in[2];
    const float* kb    = (const float*)d_in[3];
    const float* vw    = (const float*)d_in[4];
    const float* vb    = (const float*)d_in[5];
    const float* gamma = (const float*)d_in[6];
    float* out = (float*)d_out;

    const int SM128_1 = 3 * (ATILE + 128 * RSB);        // 61440
    const int SM128_2 = 3 * (2 * ATILE + 128 * RSB);    // 92160
    const int SM256_1 = 3 * (ATILE + 256 * RSB);        // 92160
    cudaFuncSetAttribute((const void*)gemm_f16<1,4,true, 256>, cudaFuncAttributeMaxDynamicSharedMemorySize, SM256_1);
    cudaFuncSetAttribute((const void*)gemm_f16<1,2,false,256>, cudaFuncAttributeMaxDynamicSharedMemorySize, SM256_1);
    cudaFuncSetAttribute((const void*)gemm_f16<1,3,false,128>, cudaFuncAttributeMaxDynamicSharedMemorySize, SM128_1);
    cudaFuncSetAttribute((const void*)gemm_f16<2,1,false,128>, cudaFuncAttributeMaxDynamicSharedMemorySize, SM128_2);

    __half *xh, *xTh, *qh, *kwh, *kwl, *vwTh, *Ph, *aTh, *W2h;
    float *pE, *pq, *pb2, *pPp;
    cudaGetSymbolAddress((void**)&xh,  g_xh);
    cudaGetSymbolAddress((void**)&xTh, g_xTh);
    cudaGetSymbolAddress((void**)&qh,  g_qh);
    cudaGetSymbolAddress((void**)&kwh, g_kwh);
    cudaGetSymbolAddress((void**)&kwl, g_kwl);
    cudaGetSymbolAddress((void**)&vwTh,g_vwTh);
    cudaGetSymbolAddress((void**)&Ph,  g_Ph);
    cudaGetSymbolAddress((void**)&aTh, g_aTh);
    cudaGetSymbolAddress((void**)&W2h, g_W2h);
    cudaGetSymbolAddress((void**)&pPp, g_Pp);
    cudaGetSymbolAddress((void**)&pE,  g_E);
    cudaGetSymbolAddress((void**)&pq,  g_qsum);
    cudaGetSymbolAddress((void**)&pb2, g_bias2);

    const long sCC = (long)CCH * CCH;
    const long sCN = (long)CCH * NPIX;

    // ---- prep (single stream) ----
    qprep_kernel<<<CCH, 256>>>(q, qh);
    xprep_kernel<<<dim3(NPIX/64, CCH/64, BATCH), 256>>>(x, xh, xTh);
    wprep_kernel<<<512, 256>>>(kw, vw, (uint2*)kwh, (uint2*)kwl, vwTh);

    // ---- GEMM1 (split-K=2, CTA 128x256): Pp[s][b][d][c] ----
    gemm_f16<1,4,true,256><<<dim3(2,4,16), 256, SM256_1>>>(
        qh, (const __half*)0, xh, NPIX, NPIX, 0, sCN, 2048,
        (__half*)0, pPp, CCH, sCC,
        (const float*)0, 0, (const float*)0, (const float*)0, (const float*)0);

    reduceP_kernel<<<(BATCH*CCH*CCH/4)/256, 256>>>(
        (const float4*)pPp, (const float4*)(pPp + BATCH*sCC), (uint2*)Ph);

    // ---- GEMM2: E[b][c][d] = sum_k kw[c][k]*P[b][d][k] + kb[c]*qsum[d] ----
    gemm_f16<2,1,false,128><<<dim3(4,4,BATCH), 256, SM128_2>>>(
        kwh, kwl, Ph, CCH, CCH, 0, sCC, CCH,
        (__half*)0, pE, CCH, sCC,
        kb, 0, pq, (const float*)0, (const float*)0);

    // ---- fused softmax + transpose, then bias2 ----
    smtrans_kernel<<<BATCH*CCH/8, 256>>>(aTh);
    bias2_kernel<<<BATCH*CCH/8, 256>>>(aTh, vb);

    // ---- GEMM3: W2[b][c][o] = sum_d attT[c][d]*vwT[o][d] ----
    gemm_f16<1,3,false,128><<<dim3(4,4,BATCH), 256, SM128_1>>>(
        aTh, (const __half*)0, vwTh, CCH, CCH, sCC, 0, CCH,
        W2h, (float*)0, CCH, sCC,
        (const float*)0, 0, (const float*)0, (const float*)0, (const float*)0);

    // ---- GEMM4 (CTA 128x256): out = gamma*(W2 @ xT + bias2) + x ----
    gemm_f16<1,2,false,256><<<dim3(16,4,BATCH), 256, SM256_1>>>(
        W2h, (const __half*)0, xTh, CCH, CCH, sCC, sCN, CCH,
        (__half*)0, out, NPIX, sCN,
        pb2, CCH, (const float*)0, x, gamma);
}

// round 14
// speedup vs baseline: 1.5852x; 1.1510x over previous
#include <cuda_runtime.h>
#include <cuda_fp16.h>
#include <stdint.h>

// ---------------------------------------------------------------------------
// Channel attention, factorized; classic tensor cores mma.m16n8k16 fp16->f32.
//   P[b]  = q @ x[b]^T                   1-MMA fp16, split-K=2 (f32 partials)
//   E[b]  = kw . P[b] + kb (x) qsum      2-MMA (kw hi/lo split)
//   att   = softmax rows(E)              fused with transpose -> aTh fp16
//   W2[b] = attT . vwT                   1-MMA
//   out   = gamma*(W2 @ xT + b2) + x     1-MMA, f32 epilogue + residual
// R14: R10 structure (128x128 CTA, 2 CTAs/SM) with BK=64 / 2-stage pipeline
//      (half the barriers, bit-identical accumulation order).
// ---------------------------------------------------------------------------

#define BATCH 8
#define CCH   512
#define NPIX  4096

__device__ __half g_xh [BATCH*CCH*NPIX];
__device__ __half g_xTh[BATCH*CCH*NPIX];
__device__ __half g_qh [CCH*NPIX];
__device__ __half g_kwh[CCH*CCH];
__device__ __half g_kwl[CCH*CCH];
__device__ __half g_vwTh[CCH*CCH];
__device__ __half g_Ph [BATCH*CCH*CCH];
__device__ __half g_aTh[BATCH*CCH*CCH];
__device__ __half g_W2h[BATCH*CCH*CCH];
__device__ float g_Pp[2*BATCH*CCH*CCH];
__device__ float g_E[BATCH*CCH*CCH];
__device__ float g_qsum[CCH];
__device__ float g_bias2[BATCH*CCH];

// --------------------------- asm helpers -----------------------------------
__device__ __forceinline__ uint32_t smem_u32(const void* p) {
    uint32_t a;
    asm("{ .reg .u64 t; cvta.to.shared.u64 t, %1; cvt.u32.u64 %0, t; }" : "=r"(a) : "l"(p));
    return a;
}
__device__ __forceinline__ void cp16(uint32_t saddr, const void* g) {
    asm volatile("cp.async.cg.shared.global [%0], [%1], 16;" :: "r"(saddr), "l"(g) : "memory");
}
__device__ __forceinline__ void cp_commit() {
    asm volatile("cp.async.commit_group;" ::: "memory");
}
template<int N>
__device__ __forceinline__ void cp_wait() {
    asm volatile("cp.async.wait_group %0;" :: "n"(N) : "memory");
}
__device__ __forceinline__ void ldsm4(uint32_t* r, uint32_t a) {
    asm volatile("ldmatrix.sync.aligned.m8n8.x4.shared.b16 {%0,%1,%2,%3}, [%4];"
                 : "=r"(r[0]), "=r"(r[1]), "=r"(r[2]), "=r"(r[3]) : "r"(a));
}
__device__ __forceinline__ void mma16816(float* d, const uint32_t* a, const uint32_t* b) {
    asm volatile("mma.sync.aligned.m16n8k16.row.col.f32.f16.f16.f32 "
                 "{%0,%1,%2,%3}, {%4,%5,%6,%7}, {%8,%9}, {%0,%1,%2,%3};"
                 : "+f"(d[0]), "+f"(d[1]), "+f"(d[2]), "+f"(d[3])
                 : "r"(a[0]), "r"(a[1]), "r"(a[2]), "r"(a[3]), "r"(b[0]), "r"(b[1]));
}
__device__ __forceinline__ uint32_t pack2(__half a, __half b) {
    __half2 p; p.x = a; p.y = b;
    return *reinterpret_cast<uint32_t*>(&p);
}

// --------------------------- GEMM kernel -----------------------------------
// CTA tile 128x128, BK=64, 2-stage cp.async double buffer (1 barrier/chunk).
// SMEM tile: 128 rows x 64 halves (128B), row padded to 144B.
// NMMA=1: tiles A,B per stage.  NMMA=2: Ah,Al,B.
#define RSB   144
#define TILEB (128*RSB)     // 18432

// EPI: 1 = f32 + e1[m]*e2[n]; 2 = gamma*(v+e1)+xres; 3 = half out; 4 = f32 plain.
template<int NMMA, int EPI, bool KSPLIT>
__global__ __launch_bounds__(256)
void gemm_f16(const __half* __restrict__ Ah, const __half* __restrict__ Al,
              const __half* __restrict__ Bh,
              int ldA, int ldB, long sA, long sB, int K,
              __half* __restrict__ Dh,
              float* __restrict__ Dout, int ldD, long sD,
              const float* __restrict__ e1, long se1,
              const float* __restrict__ e2,
              const float* __restrict__ xres,
              const float* __restrict__ gptr)
{
    constexpr int NTILES = (NMMA == 2) ? 3 : 2;
    constexpr int STGB   = NTILES * TILEB;
    constexpr int BOFF   = (NMMA == 2) ? 2 * TILEB : TILEB;

    extern __shared__ char sm[];
    const uint32_t sb = smem_u32(sm);
    const int tid = threadIdx.x, lane = tid & 31, wid = tid >> 5;
    const int wm = (wid >> 2) * 64, wn = (wid & 3) * 32;
    const int b      = KSPLIT ? (blockIdx.z & 7) : blockIdx.z;
    const int kslice = KSPLIT ? (blockIdx.z >> 3) : 0;
    const int m0 = blockIdx.y * 128, n0 = blockIdx.x * 128;

    Ah += b * sA + (long)kslice * K;
    if (NMMA == 2) Al += (long)kslice * K;
    Bh += b * sB + (long)kslice * K;
    if (KSPLIT) Dout += (long)kslice * BATCH * sD;

    const uint32_t aoff = ((lane & 7) + 8 * ((lane >> 3) & 1)) * RSB + (lane >> 4) * 16;
    const uint32_t boff = ((lane & 7) + 8 * (lane >> 4)) * RSB + ((lane >> 3) & 1) * 16;

    float acc[4][4][4];
    #pragma unroll
    for (int i = 0; i < 4; i++)
        #pragma unroll
        for (int j = 0; j < 4; j++)
            #pragma unroll
            for (int v = 0; v < 4; v++) acc[i][j][v] = 0.f;

    const int nc = K >> 6;      // 64-wide chunks

    // per-thread load coords: 1024 cp16 per tile, 4 iters of 256 threads
    // idx -> row = idx>>3 (0..127), c16 = idx&7 (16B chunk within 128B row)
    auto load_stage = [&](int stage, int k0) {
        uint32_t base = sb + stage * STGB;
        #pragma unroll
        for (int it = 0; it < 4; it++) {
            int idx = it * 256 + tid;
            int row = idx >> 3, c16 = idx & 7;
            uint32_t so = base + row * RSB + c16 * 16;
            long ga = (long)(m0 + row) * ldA + k0 + c16 * 8;
            cp16(so, Ah + ga);
            if (NMMA == 2) cp16(so + TILEB, Al + ga);
            cp16(so + BOFF, Bh + (long)(n0 + row) * ldB + k0 + c16 * 8);
        }
    };

    auto compute_stage = [&](int stage) {
        uint32_t Abase = sb + stage * STGB;
        uint32_t Bbase = Abase + BOFF;
        #pragma unroll
        for (int ks = 0; ks < 4; ks++) {
            uint32_t kb2 = ks * 32;
            uint32_t ah[4][4], al[4][4], bh[4][2];
            #pragma unroll
            for (int mi = 0; mi < 4; mi++) {
                ldsm4(ah[mi], Abase + (wm + mi * 16) * RSB + kb2 + aoff);
                if (NMMA == 2) ldsm4(al[mi], Abase + TILEB + (wm + mi * 16) * RSB + kb2 + aoff);
            }
            #pragma unroll
            for (int nb = 0; nb < 2; nb++) {
                uint32_t t[4];
                ldsm4(t, Bbase + (wn + nb * 16) * RSB + kb2 + boff);
                bh[2*nb][0] = t[0]; bh[2*nb][1] = t[1];
                bh[2*nb+1][0] = t[2]; bh[2*nb+1][1] = t[3];
            }
            #pragma unroll
            for (int mi = 0; mi < 4; mi++)
                #pragma unroll
                for (int ni = 0; ni < 4; ni++) {
                    mma16816(acc[mi][ni], ah[mi], bh[ni]);
                    if (NMMA == 2) mma16816(acc[mi][ni], al[mi], bh[ni]);
                }
        }
    };

    // 2-stage double buffer: 1 wait + 1 barrier per 64-chunk
    load_stage(0, 0);
    cp_commit();
    for (int c = 0; c < nc; c++) {
        cp_wait<0>();
        __syncthreads();
        if (c + 1 < nc) {
            load_stage((c + 1) & 1, (c + 1) * 64);
            cp_commit();
        }
        compute_stage(c & 1);
        __syncthreads();   // protect buffer (c&1) before it is overwritten at c+2
    }

    // ------------------------------ epilogue -------------------------------
    float g = 0.f;
    if (EPI == 2) g = gptr[0];
    #pragma unroll
    for (int mi = 0; mi < 4; mi++) {
        #pragma unroll
        for (int half_ = 0; half_ < 2; half_++) {
            int r = m0 + wm + mi * 16 + (lane >> 2) + half_ * 8;
            float e1r = 0.f;
            if (EPI == 1) e1r = e1[r];
            if (EPI == 2) e1r = e1[b * se1 + r];
            #pragma unroll
            for (int ni = 0; ni < 4; ni++) {
                int cidx = n0 + wn + ni * 8 + 2 * (lane & 3);
                float v0 = acc[mi][ni][half_ * 2 + 0];
                float v1 = acc[mi][ni][half_ * 2 + 1];
                long idx = (long)r * ldD + cidx;
                if (EPI == 3) {
                    __half2 ph;
                    ph.x = __float2half_rn(v0); ph.y = __float2half_rn(v1);
                    *reinterpret_cast<__half2*>(Dh + b * sD + idx) = ph;
                } else if (EPI == 4) {
                    float2 o; o.x = v0; o.y = v1;
                    *reinterpret_cast<float2*>(Dout + b * sD + idx) = o;
                } else if (EPI == 1) {
                    float2 o;
                    o.x = v0 + e1r * e2[cidx];
                    o.y = v1 + e1r * e2[cidx + 1];
                    *reinterpret_cast<float2*>(Dout + b * sD + idx) = o;
                } else {
                    float2 xr = *reinterpret_cast<const float2*>(xres + b * sD + idx);
                    float2 o;
                    o.x = g * (v0 + e1r) + xr.x;
                    o.y = g * (v1 + e1r) + xr.y;
                    *reinterpret_cast<float2*>(Dout + b * sD + idx) = o;
                }
            }
        }
    }
}

// split-K reduction: Ph = half(p0 + p1)
__global__ __launch_bounds__(256)
void reduceP_kernel(const float4* __restrict__ p0, const float4* __restrict__ p1,
                    uint2* __restrict__ Ph)
{
    int i = blockIdx.x * 256 + threadIdx.x;
    float4 a = p0[i], c = p1[i];
    uint2 u;
    u.x = pack2(__float2half_rn(a.x + c.x), __float2half_rn(a.y + c.y));
    u.y = pack2(__float2half_rn(a.z + c.z), __float2half_rn(a.w + c.w));
    Ph[i] = u;
}

// ------------------------- prep kernels ------------------------------------
// x: convert to fp16 (CxN) and transposed fp16 (NxC). 64x64 tiles, vector I/O.
__global__ __launch_bounds__(256)
void xprep_kernel(const float* __restrict__ x,
                  __half* __restrict__ xh, __half* __restrict__ xTh)
{
    __shared__ __half t[64][66];
    const int b  = blockIdx.z;
    const int n0 = blockIdx.x * 64, c0 = blockIdx.y * 64;
    const int tx = threadIdx.x & 15, ty = threadIdx.x >> 4;
    const long sb_ = (long)b * CCH * NPIX;
    const float* xb = x + sb_;

    #pragma unroll
    for (int i = 0; i < 4; i++) {
        int cl = ty + 16 * i;
        float4 v = *reinterpret_cast<const float4*>(xb + (long)(c0 + cl) * NPIX + n0 + tx * 4);
        uint32_t p0 = pack2(__float2half_rn(v.x), __float2half_rn(v.y));
        uint32_t p1 = pack2(__float2half_rn(v.z), __float2half_rn(v.w));
        uint2 u; u.x = p0; u.y = p1;
        *reinterpret_cast<uint2*>(xh + sb_ + (long)(c0 + cl) * NPIX + n0 + tx * 4) = u;
        *reinterpret_cast<uint32_t*>(&t[cl][tx * 4])     = p0;
        *reinterpret_cast<uint32_t*>(&t[cl][tx * 4 + 2]) = p1;
    }
    __syncthreads();
    #pragma unroll
    for (int i = 0; i < 4; i++) {
        int nl = ty + 16 * i;
        uint2 u;
        u.x = pack2(t[tx*4+0][nl], t[tx*4+1][nl]);
        u.y = pack2(t[tx*4+2][nl], t[tx*4+3][nl]);
        *reinterpret_cast<uint2*>(xTh + sb_ + (long)(n0 + nl) * CCH + c0 + tx * 4) = u;
    }
}

// q: convert to fp16 + row sums (qsum). One block per d row.
__global__ __launch_bounds__(256)
void qprep_kernel(const float* __restrict__ q, __half* __restrict__ qh)
{
    const int d = blockIdx.x, tid = threadIdx.x;
    const float4* row = reinterpret_cast<const float4*>(q + (long)d * NPIX);
    uint2* orow = reinterpret_cast<uint2*>(qh + (long)d * NPIX);
    float s = 0.f;
    #pragma unroll
    for (int j = 0; j < 4; j++) {
        int i = tid + j * 256;
        float4 v = row[i];
        s += v.x + v.y + v.z + v.w;
        uint2 u;
        u.x = pack2(__float2half_rn(v.x), __float2half_rn(v.y));
        u.y = pack2(__float2half_rn(v.z), __float2half_rn(v.w));
        orow[i] = u;
    }
    #pragma unroll
    for (int o = 16; o; o >>= 1) s += __shfl_xor_sync(0xffffffffu, s, o);
    __shared__ float sh[8];
    if ((tid & 31) == 0) sh[tid >> 5] = s;
    __syncthreads();
    if (tid == 0) {
        float t = 0.f;
        #pragma unroll
        for (int i = 0; i < 8; i++) t += sh[i];
        g_qsum[d] = t;
    }
}

// kw hi/lo convert (blocks 0..255) + vw transpose->fp16 (blocks 256..511)
__global__ __launch_bounds__(256)
void wprep_kernel(const float* __restrict__ kw, const float* __restrict__ vw,
                  uint2* __restrict__ kwh, uint2* __restrict__ kwl,
                  __half* __restrict__ vwTh)
{
    __shared__ float smf[32][33];
    if (blockIdx.x < 256) {
        int i = blockIdx.x * 256 + threadIdx.x;
        float4 v = reinterpret_cast<const float4*>(kw)[i];
        float f[4] = {v.x, v.y, v.z, v.w};
        __half h[4], l[4];
        #pragma unroll
        for (int j = 0; j < 4; j++) {
            h[j] = __float2half_rn(f[j]);
            l[j] = __float2half_rn(f[j] - __half2float(h[j]));
        }
        uint2 uh, ul;
        uh.x = pack2(h[0], h[1]); uh.y = pack2(h[2], h[3]);
        ul.x = pack2(l[0], l[1]); ul.y = pack2(l[2], l[3]);
        kwh[i] = uh; kwl[i] = ul;
    } else {
        int t = blockIdx.x - 256;
        int x0 = (t & 15) * 32, y0 = (t >> 4) * 32;
        int tx = threadIdx.x & 31, ty = threadIdx.x >> 5;
        #pragma unroll
        for (int i = 0; i < 4; i++)
            smf[ty + i * 8][tx] = vw[(long)(y0 + ty + i * 8) * CCH + x0 + tx];
        __syncthreads();
        #pragma unroll
        for (int i = 0; i < 4; i++)
            vwTh[(long)(x0 + ty + i * 8) * CCH + y0 + tx] = __float2half_rn(smf[tx][ty + i * 8]);
    }
}

// fused softmax (rows of g_E) + transposed fp16 write to aTh
__global__ __launch_bounds__(256)
void smtrans_kernel(__half* __restrict__ aTh)
{
    __shared__ __half s[8][512];
    const int w = threadIdx.x >> 5, lane = threadIdx.x & 31;
    const long r = (long)blockIdx.x * 8 + w;
    const float* row = g_E + r * CCH;

    float v[16];
    float m = -1e30f;
    #pragma unroll
    for (int k = 0; k < 16; k++) { v[k] = row[lane + 32 * k]; m = fmaxf(m, v[k]); }
    #pragma unroll
    for (int o = 16; o; o >>= 1) m = fmaxf(m, __shfl_xor_sync(0xffffffffu, m, o));
    float ss = 0.f;
    #pragma unroll
    for (int k = 0; k < 16; k++) { v[k] = expf(v[k] - m); ss += v[k]; }
    #pragma unroll
    for (int o = 16; o; o >>= 1) ss += __shfl_xor_sync(0xffffffffu, ss, o);
    float inv = 1.f / ss;
    #pragma unroll
    for (int k = 0; k < 16; k++)
        s[w][lane + 32 * k] = __float2half_rn(v[k] * inv);
    __syncthreads();

    const int b  = (blockIdx.x * 8) >> 9;
    const int c0 = (blockIdx.x * 8) & 511;
    __half* out = aTh + (long)b * CCH * CCH + c0;
    #pragma unroll
    for (int dd = 0; dd < 2; dd++) {
        int d = 2 * threadIdx.x + dd;
        uint4 u;
        u.x = pack2(s[0][d], s[1][d]);
        u.y = pack2(s[2][d], s[3][d]);
        u.z = pack2(s[4][d], s[5][d]);
        u.w = pack2(s[6][d], s[7][d]);
        *reinterpret_cast<uint4*>(out + (long)d * CCH) = u;
    }
}

// bias2[b,c] = sum_d aTh[(b,c)][d]*vb[d]
__global__ __launch_bounds__(256)
void bias2_kernel(const __half* __restrict__ aTh, const float* __restrict__ vb)
{
    const int row = blockIdx.x * 8 + (threadIdx.x >> 5);
    const int lane = threadIdx.x & 31;
    const __half* ar = aTh + (long)row * CCH;
    float s = 0.f;
    #pragma unroll
    for (int k = 0; k < 16; k++) {
        int d = lane + 32 * k;
        s += __half2float(ar[d]) * vb[d];
    }
    #pragma unroll
    for (int o = 16; o; o >>= 1) s += __shfl_xor_sync(0xffffffffu, s, o);
    if (lane == 0) g_bias2[row] = s;
}

// ---------------------------------------------------------------------------
extern "C" void kernel_launch(void* const* d_in, const int* in_sizes, int n_in,
                              void* d_out, int out_size)
{
    const float* x     = (const float*)d_in[0];
    const float* q     = (const float*)d_in[1];
    const float* kw    = (const float*)d_in[2];
    const float* kb    = (const float*)d_in[3];
    const float* vw    = (const float*)d_in[4];
    const float* vb    = (const float*)d_in[5];
    const float* gamma = (const float*)d_in[6];
    float* out = (float*)d_out;

    const int SM1 = 2 * 2 * TILEB;   // 73728
    const int SM2 = 2 * 3 * TILEB;   // 110592
    cudaFuncSetAttribute((const void*)gemm_f16<1,4,true>,  cudaFuncAttributeMaxDynamicSharedMemorySize, SM1);
    cudaFuncSetAttribute((const void*)gemm_f16<1,2,false>, cudaFuncAttributeMaxDynamicSharedMemorySize, SM1);
    cudaFuncSetAttribute((const void*)gemm_f16<1,3,false>, cudaFuncAttributeMaxDynamicSharedMemorySize, SM1);
    cudaFuncSetAttribute((const void*)gemm_f16<2,1,false>, cudaFuncAttributeMaxDynamicSharedMemorySize, SM2);

    __half *xh, *xTh, *qh, *kwh, *kwl, *vwTh, *Ph, *aTh, *W2h;
    float *pE, *pq, *pb2, *pPp;
    cudaGetSymbolAddress((void**)&xh,  g_xh);
    cudaGetSymbolAddress((void**)&xTh, g_xTh);
    cudaGetSymbolAddress((void**)&qh,  g_qh);
    cudaGetSymbolAddress((void**)&kwh, g_kwh);
    cudaGetSymbolAddress((void**)&kwl, g_kwl);
    cudaGetSymbolAddress((void**)&vwTh,g_vwTh);
    cudaGetSymbolAddress((void**)&Ph,  g_Ph);
    cudaGetSymbolAddress((void**)&aTh, g_aTh);
    cudaGetSymbolAddress((void**)&W2h, g_W2h);
    cudaGetSymbolAddress((void**)&pPp, g_Pp);
    cudaGetSymbolAddress((void**)&pE,  g_E);
    cudaGetSymbolAddress((void**)&pq,  g_qsum);
    cudaGetSymbolAddress((void**)&pb2, g_bias2);

    const long sCC = (long)CCH * CCH;
    const long sCN = (long)CCH * NPIX;

    // ---- prep (single stream) ----
    qprep_kernel<<<CCH, 256>>>(q, qh);
    xprep_kernel<<<dim3(NPIX/64, CCH/64, BATCH), 256>>>(x, xh, xTh);
    wprep_kernel<<<512, 256>>>(kw, vw, (uint2*)kwh, (uint2*)kwl, vwTh);

    // ---- GEMM1 (split-K=2): Pp[s][b][d][c] = sum_{n in slice s} q[d][n]*x[b][c][n] ----
    gemm_f16<1,4,true><<<dim3(4,4,16), 256, SM1>>>(
        qh, (const __half*)0, xh, NPIX, NPIX, 0, sCN, 2048,
        (__half*)0, pPp, CCH, sCC,
        (const float*)0, 0, (const float*)0, (const float*)0, (const float*)0);

    reduceP_kernel<<<(BATCH*CCH*CCH/4)/256, 256>>>(
        (const float4*)pPp, (const float4*)(pPp + BATCH*sCC), (uint2*)Ph);

    // ---- GEMM2: E[b][c][d] = sum_k kw[c][k]*P[b][d][k] + kb[c]*qsum[d] ----
    gemm_f16<2,1,false><<<dim3(4,4,BATCH), 256, SM2>>>(
        kwh, kwl, Ph, CCH, CCH, 0, sCC, CCH,
        (__half*)0, pE, CCH, sCC,
        kb, 0, pq, (const float*)0, (const float*)0);

    // ---- fused softmax + transpose, then bias2 ----
    smtrans_kernel<<<BATCH*CCH/8, 256>>>(aTh);
    bias2_kernel<<<BATCH*CCH/8, 256>>>(aTh, vb);

    // ---- GEMM3: W2[b][c][o] = sum_d attT[c][d]*vwT[o][d] ----
    gemm_f16<1,3,false><<<dim3(4,4,BATCH), 256, SM1>>>(
        aTh, (const __half*)0, vwTh, CCH, CCH, sCC, 0, CCH,
        W2h, (float*)0, CCH, sCC,
        (const float*)0, 0, (const float*)0, (const float*)0, (const float*)0);

    // ---- GEMM4: out = gamma*(W2 @ xT + bias2) + x ----
    gemm_f16<1,2,false><<<dim3(NPIX/128, 4, BATCH), 256, SM1>>>(
        W2h, (const __half*)0, xTh, CCH, CCH, sCC, sCN, CCH,
        (__half*)0, out, NPIX, sCN,
        pb2, CCH, (const float*)0, x, gamma);
}